// round 1
// baseline (speedup 1.0000x reference)
#include <cuda_runtime.h>

// Shapes (fixed by the problem)
#define NEF   64
#define NNF   128
#define NGF   64
#define IN_CH 384
#define HID   128
#define TGT   64

#define TILE_E 64
#define XSW 388          // padded row stride (floats) for x tile: 4*388 % 32 != 0 (bank-safe), mult of 4 (f4 aligned)
#define HSW 140          // padded row stride for h tile
#define XS_OFF 0
#define XS_BYTES (TILE_E * XSW * 4)              // 99328
#define WS_OFF  XS_BYTES                         // W1 chunk [32][128]
#define WS_BYTES (32 * 128 * 4)                  // 16384
#define HS_OFF  (WS_OFF + WS_BYTES)              // 115712
#define HS_BYTES (TILE_E * HSW * 4)              // 35840
#define SMEM_BYTES (HS_OFF + HS_BYTES)           // 151552

__device__ __forceinline__ unsigned long long pk2(float lo, float hi) {
    unsigned long long r;
    asm("mov.b64 %0, {%1, %2};" : "=l"(r) : "f"(lo), "f"(hi));
    return r;
}
__device__ __forceinline__ void upk2(float& lo, float& hi, unsigned long long v) {
    asm("mov.b64 {%0, %1}, %2;" : "=f"(lo), "=f"(hi) : "l"(v));
}
// Packed dual-FMA: only reachable via PTX fma.rn.f32x2 (ptxas never auto-fuses)
#define FMA2(d, a, b, c) \
    asm("fma.rn.f32x2 %0, %1, %2, %3;" : "=l"(d) : "l"(a), "l"(b), "l"(c))

__global__ __launch_bounds__(256, 1)
void edge_mlp_kernel(const float* __restrict__ ek,
                     const float* __restrict__ vrk,
                     const float* __restrict__ vsk,
                     const float* __restrict__ u,
                     const void*  __restrict__ batchv,
                     const float* __restrict__ W1,
                     const float* __restrict__ b1,
                     const float* __restrict__ W2,
                     const float* __restrict__ b2,
                     float* __restrict__ out,
                     int E)
{
    extern __shared__ char smem[];
    float* xs  = (float*)(smem + XS_OFF);
    float* ws  = (float*)(smem + WS_OFF);
    float* hs  = (float*)(smem + HS_OFF);
    float* w2s = (float*)(smem + XS_OFF);   // W2 reuses x-tile region after layer 1

    const int tid = threadIdx.x;
    const int tx  = tid & 15;     // 16 column-groups
    const int ty  = tid >> 4;     // 16 row-groups
    const int r0  = ty * 4;       // 4 rows per thread
    const int c0  = tx * 8;       // layer-1: 8 cols per thread
    const int c2  = tx * 4;       // layer-2: 4 cols per thread
    const int e0  = blockIdx.x * TILE_E;

    // batch dtype sniff: jax may emit int32 (x64 disabled) or int64.
    // If int64 (LE), the int32 word at index E-1 is the high half of element
    // (E-1)/2 == 0 (values < 256). If int32, it's the sorted max (> 0).
    const int*       b32 = (const int*)batchv;
    const long long* b64 = (const long long*)batchv;
    const bool is64 = (b32[E - 1] == 0);

    // ---- gather x tile [64, 384] = concat(ek, vrk, vsk, u[batch]) ----
    #pragma unroll
    for (int it = 0; it < 24; ++it) {
        int idx = tid + it * 256;        // float4 index in tile, 0..6143
        int r   = idx / 96;              // 96 float4s per row
        int c   = (idx - r * 96) * 4;    // float column
        int e   = e0 + r; if (e > E - 1) e = E - 1;
        float4 v;
        if (c < 64) {
            v = *(const float4*)&ek[(size_t)e * NEF + c];
        } else if (c < 192) {
            v = *(const float4*)&vrk[(size_t)e * NNF + (c - 64)];
        } else if (c < 320) {
            v = *(const float4*)&vsk[(size_t)e * NNF + (c - 192)];
        } else {
            long long g = is64 ? b64[e] : (long long)b32[e];
            v = *(const float4*)&u[(size_t)g * NGF + (c - 320)];
        }
        *(float4*)&xs[r * XSW + c] = v;
    }

    // ---- layer 1: h = relu(x @ W1 + b1), 4x8 microtile, packed f32x2 ----
    unsigned long long acc[4][4];
    #pragma unroll
    for (int i = 0; i < 4; ++i)
        #pragma unroll
        for (int j = 0; j < 4; ++j) acc[i][j] = 0ull;

    for (int kt = 0; kt < IN_CH / 32; ++kt) {
        __syncthreads();   // (1st iter: gather done; later: prev FMA reads of ws done)
        // stage W1 chunk [32][128]
        #pragma unroll
        for (int j = 0; j < 4; ++j) {
            int f4 = tid + j * 256;      // 0..1023
            ((float4*)ws)[f4] = ((const float4*)(W1 + (size_t)kt * 32 * HID))[f4];
        }
        __syncthreads();

        #pragma unroll 8
        for (int kk = 0; kk < 32; ++kk) {
            const int kcol = kt * 32 + kk;
            float4 blo = *(float4*)&ws[kk * HID + c0];
            float4 bhi = *(float4*)&ws[kk * HID + c0 + 4];
            unsigned long long bb0 = pk2(blo.x, blo.y);
            unsigned long long bb1 = pk2(blo.z, blo.w);
            unsigned long long bb2 = pk2(bhi.x, bhi.y);
            unsigned long long bb3 = pk2(bhi.z, bhi.w);
            #pragma unroll
            for (int i = 0; i < 4; ++i) {
                float a = xs[(r0 + i) * XSW + kcol];
                unsigned long long a2 = pk2(a, a);
                FMA2(acc[i][0], a2, bb0, acc[i][0]);
                FMA2(acc[i][1], a2, bb1, acc[i][1]);
                FMA2(acc[i][2], a2, bb2, acc[i][2]);
                FMA2(acc[i][3], a2, bb3, acc[i][3]);
            }
        }
    }

    // epilogue L1: bias + relu -> hs
    float bias1[8];
    #pragma unroll
    for (int j = 0; j < 8; ++j) bias1[j] = b1[c0 + j];
    #pragma unroll
    for (int i = 0; i < 4; ++i) {
        float h[8];
        #pragma unroll
        for (int j = 0; j < 4; ++j) {
            float lo, hi; upk2(lo, hi, acc[i][j]);
            h[2*j]   = fmaxf(lo + bias1[2*j],   0.f);
            h[2*j+1] = fmaxf(hi + bias1[2*j+1], 0.f);
        }
        *(float4*)&hs[(r0 + i) * HSW + c0]     = make_float4(h[0], h[1], h[2], h[3]);
        *(float4*)&hs[(r0 + i) * HSW + c0 + 4] = make_float4(h[4], h[5], h[6], h[7]);
    }
    __syncthreads();

    // stage W2 [128][64] into reused region
    #pragma unroll
    for (int j = 0; j < 8; ++j) {
        int f4 = tid + j * 256;          // 0..2047
        ((float4*)w2s)[f4] = ((const float4*)W2)[f4];
    }
    __syncthreads();

    // ---- layer 2: out = h @ W2 + b2, 4x4 microtile ----
    unsigned long long acc2[4][2];
    #pragma unroll
    for (int i = 0; i < 4; ++i) { acc2[i][0] = 0ull; acc2[i][1] = 0ull; }

    #pragma unroll 8
    for (int kk = 0; kk < HID; ++kk) {
        float4 b = *(float4*)&w2s[kk * TGT + c2];
        unsigned long long bb0 = pk2(b.x, b.y);
        unsigned long long bb1 = pk2(b.z, b.w);
        #pragma unroll
        for (int i = 0; i < 4; ++i) {
            float a = hs[(r0 + i) * HSW + kk];
            unsigned long long a2 = pk2(a, a);
            FMA2(acc2[i][0], a2, bb0, acc2[i][0]);
            FMA2(acc2[i][1], a2, bb1, acc2[i][1]);
        }
    }

    float bias2[4];
    #pragma unroll
    for (int j = 0; j < 4; ++j) bias2[j] = b2[c2 + j];
    #pragma unroll
    for (int i = 0; i < 4; ++i) {
        int e = e0 + r0 + i;
        if (e < E) {
            float l0, h0, l1, h1;
            upk2(l0, h0, acc2[i][0]);
            upk2(l1, h1, acc2[i][1]);
            *(float4*)&out[(size_t)e * TGT + c2] =
                make_float4(l0 + bias2[0], h0 + bias2[1],
                            l1 + bias2[2], h1 + bias2[3]);
        }
    }
}

extern "C" void kernel_launch(void* const* d_in, const int* in_sizes, int n_in,
                              void* d_out, int out_size)
{
    const float* ek    = (const float*)d_in[0];
    const float* vrk   = (const float*)d_in[1];
    const float* vsk   = (const float*)d_in[2];
    const float* u     = (const float*)d_in[3];
    const void*  batch = (const void*) d_in[4];
    const float* W1    = (const float*)d_in[5];
    const float* b1    = (const float*)d_in[6];
    const float* W2    = (const float*)d_in[7];
    const float* b2    = (const float*)d_in[8];
    float* out = (float*)d_out;

    const int E = in_sizes[0] / NEF;

    cudaFuncSetAttribute(edge_mlp_kernel,
                         cudaFuncAttributeMaxDynamicSharedMemorySize, SMEM_BYTES);

    const int grid = (E + TILE_E - 1) / TILE_E;
    edge_mlp_kernel<<<grid, 256, SMEM_BYTES>>>(ek, vrk, vsk, u, batch,
                                               W1, b1, W2, b2, out, E);
}

// round 6
// speedup vs baseline: 4.8493x; 4.8493x over previous
#include <cuda_runtime.h>
#include <cuda_bf16.h>
#include <cstdint>

// shapes
#define NEF   64
#define NNF   128
#define NGF   64
#define IN_CH 384      // 24 k-steps of 16
#define HID   128      // 16 n-tiles of 8 (L1), 8 k-steps of 16 (L2)
#define TGT   64       // 8 n-tiles of 8
#define TILE_E 128     // 8 warps x 16 rows

// W fragments, packed per (kstep, ntile, lane): uint4 {b0_hi, b1_hi, b0_lo, b1_lo}
__device__ uint4 g_w1f[24 * 16 * 32];   // 192 KB
__device__ uint4 g_w2f[8 * 8 * 32];     // 32 KB

// ---- bf16 hi/lo split helpers ----
__device__ __forceinline__ uint32_t prmt7632(uint32_t a, uint32_t b) {
    uint32_t r; asm("prmt.b32 %0, %1, %2, 0x7632;" : "=r"(r) : "r"(a), "r"(b)); return r;
}
__device__ __forceinline__ uint32_t bf16x2_rn(float hi_elem, float lo_elem) {
    uint32_t r; asm("cvt.rn.bf16x2.f32 %0, %1, %2;" : "=r"(r) : "f"(hi_elem), "f"(lo_elem)); return r;
}
// pack pair (x0 -> low half, x1 -> high half): hi = truncated bf16, lo = bf16(residual)
__device__ __forceinline__ void split2f(float x0, float x1, uint32_t& h, uint32_t& l) {
    uint32_t u0 = __float_as_uint(x0), u1 = __float_as_uint(x1);
    h = prmt7632(u0, u1);
    float r0 = x0 - __uint_as_float(u0 & 0xFFFF0000u);
    float r1 = x1 - __uint_as_float(u1 & 0xFFFF0000u);
    l = bf16x2_rn(r1, r0);
}
__device__ __forceinline__ void split2(float2 v, uint32_t& h, uint32_t& l) {
    split2f(v.x, v.y, h, l);
}

// mma.sync m16n8k16 bf16 (baseline PTX, works on compute_103 without 'a')
#define MMA(d, a0, a1, a2, a3, b0, b1) \
    asm volatile("mma.sync.aligned.m16n8k16.row.col.f32.bf16.bf16.f32 " \
        "{%0,%1,%2,%3}, {%4,%5,%6,%7}, {%8,%9}, {%0,%1,%2,%3};" \
        : "+f"((d)[0]), "+f"((d)[1]), "+f"((d)[2]), "+f"((d)[3]) \
        : "r"(a0), "r"(a1), "r"(a2), "r"(a3), "r"(b0), "r"(b1))

// ---- prep: pack weights into fragment order (runs once per launch, ~3us) ----
__global__ void prep_frags(const float* __restrict__ W1, const float* __restrict__ W2) {
    int i = blockIdx.x * blockDim.x + threadIdx.x;
    if (i < 24 * 16 * 32) {
        int lane = i & 31, nt = (i >> 5) & 15, ks = i >> 9;
        int n  = nt * 8 + (lane >> 2);
        int k0 = ks * 16 + (lane & 3) * 2;
        float a0 = W1[(size_t)k0 * HID + n],       a1 = W1[(size_t)(k0 + 1) * HID + n];
        float a2 = W1[(size_t)(k0 + 8) * HID + n], a3 = W1[(size_t)(k0 + 9) * HID + n];
        uint32_t b0h, b0l, b1h, b1l;
        split2f(a0, a1, b0h, b0l);
        split2f(a2, a3, b1h, b1l);
        g_w1f[i] = make_uint4(b0h, b1h, b0l, b1l);
    } else if (i < 24 * 16 * 32 + 8 * 8 * 32) {
        int j = i - 24 * 16 * 32;
        int lane = j & 31, nt = (j >> 5) & 7, ks = j >> 8;
        int n  = nt * 8 + (lane >> 2);
        int k0 = ks * 16 + (lane & 3) * 2;
        float a0 = W2[(size_t)k0 * TGT + n],       a1 = W2[(size_t)(k0 + 1) * TGT + n];
        float a2 = W2[(size_t)(k0 + 8) * TGT + n], a3 = W2[(size_t)(k0 + 9) * TGT + n];
        uint32_t b0h, b0l, b1h, b1l;
        split2f(a0, a1, b0h, b0l);
        split2f(a2, a3, b1h, b1l);
        g_w2f[j] = make_uint4(b0h, b1h, b0l, b1l);
    }
}

// one k-step of layer 1: load 8 floats of X, split, 16 n-tiles x 3 mma
#define KSTEP(RLO, RHI, C, KS) do { \
    float2 x00 = *(const float2*)((RLO) + (C)); \
    float2 x01 = *(const float2*)((RLO) + (C) + 8); \
    float2 x10 = *(const float2*)((RHI) + (C)); \
    float2 x11 = *(const float2*)((RHI) + (C) + 8); \
    uint32_t ah0, al0, ah1, al1, ah2, al2, ah3, al3; \
    split2(x00, ah0, al0); split2(x10, ah1, al1); \
    split2(x01, ah2, al2); split2(x11, ah3, al3); \
    const uint4* wp = g_w1f + (KS) * 512 + lane; \
    _Pragma("unroll") \
    for (int nt = 0; nt < 16; ++nt) { \
        uint4 b = wp[nt * 32]; \
        MMA(acc[nt], ah0, ah1, ah2, ah3, b.x, b.y); \
        MMA(acc[nt], ah0, ah1, ah2, ah3, b.z, b.w); \
        MMA(acc[nt], al0, al1, al2, al3, b.x, b.y); \
    } \
} while (0)

__global__ __launch_bounds__(256, 2)
void edge_mlp_hmma(const float* __restrict__ ek,
                   const float* __restrict__ vrk,
                   const float* __restrict__ vsk,
                   const float* __restrict__ u,
                   const void*  __restrict__ batchv,
                   const float* __restrict__ b1,
                   const float* __restrict__ b2,
                   float* __restrict__ out,
                   int E)
{
    const int tid  = threadIdx.x;
    const int wid  = tid >> 5;
    const int lane = tid & 31;
    const int qr   = lane >> 2;        // row within 8
    const int cb   = (lane & 3) * 2;   // col pair base

    int e_lo = blockIdx.x * TILE_E + wid * 16 + qr;
    int e_hi = e_lo + 8;
    const bool st_lo = e_lo < E, st_hi = e_hi < E;
    const int el = st_lo ? e_lo : E - 1;
    const int eh = st_hi ? e_hi : E - 1;

    // batch dtype sniff: sorted values < G=256, so int64 => high word of last elem is 0
    const int* b32p = (const int*)batchv;
    const long long* b64p = (const long long*)batchv;
    const bool is64 = (b32p[E - 1] == 0);
    const long long g_lo = is64 ? b64p[el] : (long long)b32p[el];
    const long long g_hi = is64 ? b64p[eh] : (long long)b32p[eh];

    const float* ek_lo = ek  + (size_t)el * NEF;
    const float* ek_hi = ek  + (size_t)eh * NEF;
    const float* vr_lo = vrk + (size_t)el * NNF;
    const float* vr_hi = vrk + (size_t)eh * NNF;
    const float* vs_lo = vsk + (size_t)el * NNF;
    const float* vs_hi = vsk + (size_t)eh * NNF;
    const float* u_lo  = u   + (size_t)g_lo * NGF;
    const float* u_hi  = u   + (size_t)g_hi * NGF;

    // ---- layer 1: D1[16 rows x 128 cols] per warp, 16 n-tiles ----
    float acc[16][4];
    #pragma unroll
    for (int nt = 0; nt < 16; ++nt)
        #pragma unroll
        for (int j = 0; j < 4; ++j) acc[nt][j] = 0.f;

    #pragma unroll
    for (int ks = 0; ks < 4; ++ks) KSTEP(ek_lo, ek_hi, ks * 16 + cb, ks);
    #pragma unroll
    for (int ks = 0; ks < 8; ++ks) KSTEP(vr_lo, vr_hi, ks * 16 + cb, ks + 4);
    #pragma unroll
    for (int ks = 0; ks < 8; ++ks) KSTEP(vs_lo, vs_hi, ks * 16 + cb, ks + 12);
    #pragma unroll
    for (int ks = 0; ks < 4; ++ks) KSTEP(u_lo, u_hi, ks * 16 + cb, ks + 20);

    // ---- epilogue 1 in registers: bias + relu + split -> layer-2 A fragments ----
    // C-frag (m16n8) layout == A-frag (m16n8k16) layout: nt pair (2j, 2j+1) => k-step j
    uint32_t hh[8][4], hl[8][4];
    #pragma unroll
    for (int j = 0; j < 8; ++j) {
        float2 bA = *(const float2*)(b1 + 16 * j + cb);
        float2 bB = *(const float2*)(b1 + 16 * j + 8 + cb);
        float v00 = fmaxf(acc[2*j][0]   + bA.x, 0.f);
        float v01 = fmaxf(acc[2*j][1]   + bA.y, 0.f);
        float v10 = fmaxf(acc[2*j][2]   + bA.x, 0.f);
        float v11 = fmaxf(acc[2*j][3]   + bA.y, 0.f);
        float w00 = fmaxf(acc[2*j+1][0] + bB.x, 0.f);
        float w01 = fmaxf(acc[2*j+1][1] + bB.y, 0.f);
        float w10 = fmaxf(acc[2*j+1][2] + bB.x, 0.f);
        float w11 = fmaxf(acc[2*j+1][3] + bB.y, 0.f);
        split2f(v00, v01, hh[j][0], hl[j][0]);   // a0: row lo, k lo
        split2f(v10, v11, hh[j][1], hl[j][1]);   // a1: row hi, k lo
        split2f(w00, w01, hh[j][2], hl[j][2]);   // a2: row lo, k hi
        split2f(w10, w11, hh[j][3], hl[j][3]);   // a3: row hi, k hi
    }

    // ---- layer 2: D2[16 x 64] per warp, 8 n-tiles, K=128 (8 k-steps) ----
    float acc2[8][4];
    #pragma unroll
    for (int nt = 0; nt < 8; ++nt)
        #pragma unroll
        for (int j = 0; j < 4; ++j) acc2[nt][j] = 0.f;

    #pragma unroll
    for (int ks = 0; ks < 8; ++ks) {
        const uint4* wp = g_w2f + ks * 256 + lane;
        #pragma unroll
        for (int nt = 0; nt < 8; ++nt) {
            uint4 b = wp[nt * 32];
            MMA(acc2[nt], hh[ks][0], hh[ks][1], hh[ks][2], hh[ks][3], b.x, b.y);
            MMA(acc2[nt], hh[ks][0], hh[ks][1], hh[ks][2], hh[ks][3], b.z, b.w);
            MMA(acc2[nt], hl[ks][0], hl[ks][1], hl[ks][2], hl[ks][3], b.x, b.y);
        }
    }

    // ---- store: + b2 ----
    #pragma unroll
    for (int nt = 0; nt < 8; ++nt) {
        float2 bb = *(const float2*)(b2 + nt * 8 + cb);
        if (st_lo)
            *(float2*)(out + (size_t)e_lo * TGT + nt * 8 + cb) =
                make_float2(acc2[nt][0] + bb.x, acc2[nt][1] + bb.y);
        if (st_hi)
            *(float2*)(out + (size_t)e_hi * TGT + nt * 8 + cb) =
                make_float2(acc2[nt][2] + bb.x, acc2[nt][3] + bb.y);
    }
}

extern "C" void kernel_launch(void* const* d_in, const int* in_sizes, int n_in,
                              void* d_out, int out_size)
{
    const float* ek    = (const float*)d_in[0];
    const float* vrk   = (const float*)d_in[1];
    const float* vsk   = (const float*)d_in[2];
    const float* u     = (const float*)d_in[3];
    const void*  batch = (const void*) d_in[4];
    const float* W1    = (const float*)d_in[5];
    const float* b1    = (const float*)d_in[6];
    const float* W2    = (const float*)d_in[7];
    const float* b2    = (const float*)d_in[8];
    float* out = (float*)d_out;

    const int E = in_sizes[0] / NEF;

    prep_frags<<<(24 * 16 * 32 + 8 * 8 * 32 + 255) / 256, 256>>>(W1, W2);

    const int grid = (E + TILE_E - 1) / TILE_E;
    edge_mlp_hmma<<<grid, 256>>>(ek, vrk, vsk, u, batch, b1, b2, out, E);
}

// round 10
// speedup vs baseline: 6.2607x; 1.2911x over previous
#include <cuda_runtime.h>
#include <cuda_fp16.h>
#include <cstdint>

// shapes
#define NEF   64
#define NNF   128
#define NGF   64
#define IN_CH 384      // 24 k-steps of 16
#define HID   128      // 16 n-tiles of 8 (L1); 8 k-steps of 16 (L2)
#define TGT   64       // 8 n-tiles of 8
#define TILE_E 64      // 4 warps x 16 rows

// W fragments fp16, packed per (kstep, ntile, lane): uint2 {b0, b1}
__device__ uint2 g_w1f[24 * 16 * 32];   // 96 KB  (fits in L1)
__device__ uint2 g_w2f[8 * 8 * 32];     // 16 KB

// pack two floats into f16x2: x0 -> low half, x1 -> high half
__device__ __forceinline__ uint32_t f16x2(float x0, float x1) {
    uint32_t r; asm("cvt.rn.f16x2.f32 %0, %1, %2;" : "=r"(r) : "f"(x1), "f"(x0)); return r;
}
__device__ __forceinline__ uint32_t f16x2v(float2 v) { return f16x2(v.x, v.y); }

// mma.sync m16n8k16 fp16, f32 accum (baseline PTX, sm_80+)
#define MMA(d, a0, a1, a2, a3, b0, b1) \
    asm volatile("mma.sync.aligned.m16n8k16.row.col.f32.f16.f16.f32 " \
        "{%0,%1,%2,%3}, {%4,%5,%6,%7}, {%8,%9}, {%0,%1,%2,%3};" \
        : "+f"((d)[0]), "+f"((d)[1]), "+f"((d)[2]), "+f"((d)[3]) \
        : "r"(a0), "r"(a1), "r"(a2), "r"(a3), "r"(b0), "r"(b1))

// ---- prep: pack weights into fragment order (runs once per launch) ----
__global__ void prep_frags(const float* __restrict__ W1, const float* __restrict__ W2) {
    int i = blockIdx.x * blockDim.x + threadIdx.x;
    if (i < 24 * 16 * 32) {
        int lane = i & 31, nt = (i >> 5) & 15, ks = i >> 9;
        int n  = nt * 8 + (lane >> 2);
        int k0 = ks * 16 + (lane & 3) * 2;
        uint32_t b0 = f16x2(W1[(size_t)k0 * HID + n],       W1[(size_t)(k0 + 1) * HID + n]);
        uint32_t b1 = f16x2(W1[(size_t)(k0 + 8) * HID + n], W1[(size_t)(k0 + 9) * HID + n]);
        g_w1f[i] = make_uint2(b0, b1);
    } else if (i < 24 * 16 * 32 + 8 * 8 * 32) {
        int j = i - 24 * 16 * 32;
        int lane = j & 31, nt = (j >> 5) & 7, ks = j >> 8;
        int n  = nt * 8 + (lane >> 2);
        int k0 = ks * 16 + (lane & 3) * 2;
        uint32_t b0 = f16x2(W2[(size_t)k0 * TGT + n],       W2[(size_t)(k0 + 1) * TGT + n]);
        uint32_t b1 = f16x2(W2[(size_t)(k0 + 8) * TGT + n], W2[(size_t)(k0 + 9) * TGT + n]);
        g_w2f[j] = make_uint2(b0, b1);
    }
}

// one k-step of layer 1: load 8 floats of X per row-half, convert, 16 n-tiles x 1 mma
#define KSTEP(RLO, RHI, C, KS) do { \
    uint32_t a0 = f16x2v(*(const float2*)((RLO) + (C))); \
    uint32_t a2 = f16x2v(*(const float2*)((RLO) + (C) + 8)); \
    uint32_t a1 = f16x2v(*(const float2*)((RHI) + (C))); \
    uint32_t a3 = f16x2v(*(const float2*)((RHI) + (C) + 8)); \
    const uint2* wp = g_w1f + (KS) * 512 + lane; \
    _Pragma("unroll") \
    for (int nt = 0; nt < 16; ++nt) { \
        uint2 b = wp[nt * 32]; \
        MMA(acc[nt], a0, a1, a2, a3, b.x, b.y); \
    } \
} while (0)

__global__ __launch_bounds__(128, 5)
void edge_mlp_hmma(const float* __restrict__ ek,
                   const float* __restrict__ vrk,
                   const float* __restrict__ vsk,
                   const float* __restrict__ u,
                   const void*  __restrict__ batchv,
                   const float* __restrict__ b1,
                   const float* __restrict__ b2,
                   float* __restrict__ out,
                   int E)
{
    const int tid  = threadIdx.x;
    const int wid  = tid >> 5;
    const int lane = tid & 31;
    const int qr   = lane >> 2;        // row within 8
    const int cb   = (lane & 3) * 2;   // col pair base

    int e_lo = blockIdx.x * TILE_E + wid * 16 + qr;
    int e_hi = e_lo + 8;
    const bool st_lo = e_lo < E, st_hi = e_hi < E;
    const int el = st_lo ? e_lo : E - 1;
    const int eh = st_hi ? e_hi : E - 1;

    // batch dtype sniff: sorted values < G=256, so int64 => high word of last elem is 0
    const int* b32p = (const int*)batchv;
    const long long* b64p = (const long long*)batchv;
    const bool is64 = (b32p[E - 1] == 0);
    const long long g_lo = is64 ? b64p[el] : (long long)b32p[el];
    const long long g_hi = is64 ? b64p[eh] : (long long)b32p[eh];

    const float* ek_lo = ek  + (size_t)el * NEF;
    const float* ek_hi = ek  + (size_t)eh * NEF;
    const float* vr_lo = vrk + (size_t)el * NNF;
    const float* vr_hi = vrk + (size_t)eh * NNF;
    const float* vs_lo = vsk + (size_t)el * NNF;
    const float* vs_hi = vsk + (size_t)eh * NNF;
    const float* u_lo  = u   + (size_t)g_lo * NGF;
    const float* u_hi  = u   + (size_t)g_hi * NGF;

    // ---- layer 1: D1[16 rows x 128 cols] per warp ----
    float acc[16][4];
    #pragma unroll
    for (int nt = 0; nt < 16; ++nt)
        #pragma unroll
        for (int j = 0; j < 4; ++j) acc[nt][j] = 0.f;

    #pragma unroll
    for (int ks = 0; ks < 4; ++ks) KSTEP(ek_lo, ek_hi, ks * 16 + cb, ks);
    #pragma unroll
    for (int ks = 0; ks < 8; ++ks) KSTEP(vr_lo, vr_hi, ks * 16 + cb, ks + 4);
    #pragma unroll
    for (int ks = 0; ks < 8; ++ks) KSTEP(vs_lo, vs_hi, ks * 16 + cb, ks + 12);
    #pragma unroll
    for (int ks = 0; ks < 4; ++ks) KSTEP(u_lo, u_hi, ks * 16 + cb, ks + 20);

    // ---- epilogue 1 in registers: bias + relu + cvt -> layer-2 A fragments ----
    // C-frag (m16n8) layout == A-frag (m16n8k16) layout: nt pair (2j, 2j+1) => k-step j
    uint32_t hh[8][4];
    #pragma unroll
    for (int j = 0; j < 8; ++j) {
        float2 bA = *(const float2*)(b1 + 16 * j + cb);
        float2 bB = *(const float2*)(b1 + 16 * j + 8 + cb);
        float v00 = fmaxf(acc[2*j][0]   + bA.x, 0.f);
        float v01 = fmaxf(acc[2*j][1]   + bA.y, 0.f);
        float v10 = fmaxf(acc[2*j][2]   + bA.x, 0.f);
        float v11 = fmaxf(acc[2*j][3]   + bA.y, 0.f);
        float w00 = fmaxf(acc[2*j+1][0] + bB.x, 0.f);
        float w01 = fmaxf(acc[2*j+1][1] + bB.y, 0.f);
        float w10 = fmaxf(acc[2*j+1][2] + bB.x, 0.f);
        float w11 = fmaxf(acc[2*j+1][3] + bB.y, 0.f);
        hh[j][0] = f16x2(v00, v01);   // a0: row lo, k lo
        hh[j][1] = f16x2(v10, v11);   // a1: row hi, k lo
        hh[j][2] = f16x2(w00, w01);   // a2: row lo, k hi
        hh[j][3] = f16x2(w10, w11);   // a3: row hi, k hi
    }

    // ---- layer 2: D2[16 x 64] per warp, 8 n-tiles, K=128 (8 k-steps) ----
    float acc2[8][4];
    #pragma unroll
    for (int nt = 0; nt < 8; ++nt)
        #pragma unroll
        for (int j = 0; j < 4; ++j) acc2[nt][j] = 0.f;

    #pragma unroll
    for (int ks = 0; ks < 8; ++ks) {
        const uint2* wp = g_w2f + ks * 256 + lane;
        #pragma unroll
        for (int nt = 0; nt < 8; ++nt) {
            uint2 b = wp[nt * 32];
            MMA(acc2[nt], hh[ks][0], hh[ks][1], hh[ks][2], hh[ks][3], b.x, b.y);
        }
    }

    // ---- store: + b2 ----
    #pragma unroll
    for (int nt = 0; nt < 8; ++nt) {
        float2 bb = *(const float2*)(b2 + nt * 8 + cb);
        if (st_lo)
            *(float2*)(out + (size_t)e_lo * TGT + nt * 8 + cb) =
                make_float2(acc2[nt][0] + bb.x, acc2[nt][1] + bb.y);
        if (st_hi)
            *(float2*)(out + (size_t)e_hi * TGT + nt * 8 + cb) =
                make_float2(acc2[nt][2] + bb.x, acc2[nt][3] + bb.y);
    }
}

extern "C" void kernel_launch(void* const* d_in, const int* in_sizes, int n_in,
                              void* d_out, int out_size)
{
    const float* ek    = (const float*)d_in[0];
    const float* vrk   = (const float*)d_in[1];
    const float* vsk   = (const float*)d_in[2];
    const float* u     = (const float*)d_in[3];
    const void*  batch = (const void*) d_in[4];
    const float* W1    = (const float*)d_in[5];
    const float* b1    = (const float*)d_in[6];
    const float* W2    = (const float*)d_in[7];
    const float* b2    = (const float*)d_in[8];
    float* out = (float*)d_out;

    const int E = in_sizes[0] / NEF;

    prep_frags<<<(24 * 16 * 32 + 8 * 8 * 32 + 255) / 256, 256>>>(W1, W2);

    const int grid = (E + TILE_E - 1) / TILE_E;
    edge_mlp_hmma<<<grid, 128>>>(ek, vrk, vsk, u, batch, b1, b2, out, E);
}

// round 14
// speedup vs baseline: 11.2745x; 1.8008x over previous
#include <cuda_runtime.h>
#include <cuda_fp16.h>
#include <cstdint>

// shapes
#define NEF   64
#define NNF   128
#define NGF   64
#define IN_CH 384      // 24 k-steps of 16
#define HID   128      // 16 n-tiles of 8 (L1); 8 k-steps of 16 (L2)
#define TGT   64       // 8 n-tiles of 8
#define TILE_E 64      // 4 warps x 16 rows

// W fragments fp16, packed per (kstep, ntile-pair, lane):
// uint4 {nt_even.b0, nt_even.b1, nt_odd.b0, nt_odd.b1}
__device__ uint4 g_w1f4[24 * 8 * 32];   // 96 KB (fits in L1)
__device__ uint4 g_w2f4[8 * 4 * 32];    // 16 KB

// pack two floats into f16x2: x0 -> low half, x1 -> high half
__device__ __forceinline__ uint32_t f16x2(float x0, float x1) {
    uint32_t r; asm("cvt.rn.f16x2.f32 %0, %1, %2;" : "=r"(r) : "f"(x1), "f"(x0)); return r;
}
__device__ __forceinline__ uint32_t f16x2v(float2 v) { return f16x2(v.x, v.y); }

// mma.sync m16n8k16 fp16, f32 accum (baseline PTX, sm_80+)
#define MMA(d, a0, a1, a2, a3, b0, b1) \
    asm volatile("mma.sync.aligned.m16n8k16.row.col.f32.f16.f16.f32 " \
        "{%0,%1,%2,%3}, {%4,%5,%6,%7}, {%8,%9}, {%0,%1,%2,%3};" \
        : "+f"((d)[0]), "+f"((d)[1]), "+f"((d)[2]), "+f"((d)[3]) \
        : "r"(a0), "r"(a1), "r"(a2), "r"(a3), "r"(b0), "r"(b1))

// ---- prep: pack weights into uint4 fragment order (once per launch) ----
__global__ void prep_frags(const float* __restrict__ W1, const float* __restrict__ W2) {
    int i = blockIdx.x * blockDim.x + threadIdx.x;
    if (i < 24 * 8 * 32) {
        int lane = i & 31, ntp = (i >> 5) & 7, ks = i >> 8;
        int qn = lane >> 2;
        int n0 = (2 * ntp) * 8 + qn;
        int n1 = (2 * ntp + 1) * 8 + qn;
        int k0 = ks * 16 + (lane & 3) * 2;
        uint4 v;
        v.x = f16x2(W1[(size_t)k0 * HID + n0],       W1[(size_t)(k0 + 1) * HID + n0]);
        v.y = f16x2(W1[(size_t)(k0 + 8) * HID + n0], W1[(size_t)(k0 + 9) * HID + n0]);
        v.z = f16x2(W1[(size_t)k0 * HID + n1],       W1[(size_t)(k0 + 1) * HID + n1]);
        v.w = f16x2(W1[(size_t)(k0 + 8) * HID + n1], W1[(size_t)(k0 + 9) * HID + n1]);
        g_w1f4[i] = v;
    } else if (i < 24 * 8 * 32 + 8 * 4 * 32) {
        int j = i - 24 * 8 * 32;
        int lane = j & 31, ntp = (j >> 5) & 3, ks = j >> 7;
        int qn = lane >> 2;
        int n0 = (2 * ntp) * 8 + qn;
        int n1 = (2 * ntp + 1) * 8 + qn;
        int k0 = ks * 16 + (lane & 3) * 2;
        uint4 v;
        v.x = f16x2(W2[(size_t)k0 * TGT + n0],       W2[(size_t)(k0 + 1) * TGT + n0]);
        v.y = f16x2(W2[(size_t)(k0 + 8) * TGT + n0], W2[(size_t)(k0 + 9) * TGT + n0]);
        v.z = f16x2(W2[(size_t)k0 * TGT + n1],       W2[(size_t)(k0 + 1) * TGT + n1]);
        v.w = f16x2(W2[(size_t)(k0 + 8) * TGT + n1], W2[(size_t)(k0 + 9) * TGT + n1]);
        g_w2f4[j] = v;
    }
}

// one k-step of layer 1: batched loads (A + 4x LDG.128), 8 MMAs, 4x LDG.128, 8 MMAs
#define KSTEP(RLO, RHI, C, KS) do { \
    float2 x00 = *(const float2*)((RLO) + (C)); \
    float2 x01 = *(const float2*)((RLO) + (C) + 8); \
    float2 x10 = *(const float2*)((RHI) + (C)); \
    float2 x11 = *(const float2*)((RHI) + (C) + 8); \
    const uint4* wp = g_w1f4 + (KS) * 256 + lane; \
    uint4 b0 = __ldg(wp);      uint4 b1 = __ldg(wp + 32); \
    uint4 b2 = __ldg(wp + 64); uint4 b3 = __ldg(wp + 96); \
    uint32_t a0 = f16x2v(x00); uint32_t a1 = f16x2v(x10); \
    uint32_t a2 = f16x2v(x01); uint32_t a3 = f16x2v(x11); \
    MMA(acc[0], a0, a1, a2, a3, b0.x, b0.y); MMA(acc[1], a0, a1, a2, a3, b0.z, b0.w); \
    MMA(acc[2], a0, a1, a2, a3, b1.x, b1.y); MMA(acc[3], a0, a1, a2, a3, b1.z, b1.w); \
    MMA(acc[4], a0, a1, a2, a3, b2.x, b2.y); MMA(acc[5], a0, a1, a2, a3, b2.z, b2.w); \
    MMA(acc[6], a0, a1, a2, a3, b3.x, b3.y); MMA(acc[7], a0, a1, a2, a3, b3.z, b3.w); \
    uint4 b4 = __ldg(wp + 128); uint4 b5 = __ldg(wp + 160); \
    uint4 b6 = __ldg(wp + 192); uint4 b7 = __ldg(wp + 224); \
    MMA(acc[8],  a0, a1, a2, a3, b4.x, b4.y); MMA(acc[9],  a0, a1, a2, a3, b4.z, b4.w); \
    MMA(acc[10], a0, a1, a2, a3, b5.x, b5.y); MMA(acc[11], a0, a1, a2, a3, b5.z, b5.w); \
    MMA(acc[12], a0, a1, a2, a3, b6.x, b6.y); MMA(acc[13], a0, a1, a2, a3, b6.z, b6.w); \
    MMA(acc[14], a0, a1, a2, a3, b7.x, b7.y); MMA(acc[15], a0, a1, a2, a3, b7.z, b7.w); \
} while (0)

__global__ __launch_bounds__(128, 4)
void edge_mlp_hmma(const float* __restrict__ ek,
                   const float* __restrict__ vrk,
                   const float* __restrict__ vsk,
                   const float* __restrict__ u,
                   const void*  __restrict__ batchv,
                   const float* __restrict__ b1,
                   const float* __restrict__ b2,
                   float* __restrict__ out,
                   int E)
{
    const int tid  = threadIdx.x;
    const int wid  = tid >> 5;
    const int lane = tid & 31;
    const int qr   = lane >> 2;        // row within 8
    const int cb   = (lane & 3) * 2;   // col pair base

    int e_lo = blockIdx.x * TILE_E + wid * 16 + qr;
    int e_hi = e_lo + 8;
    const bool st_lo = e_lo < E, st_hi = e_hi < E;
    const int el = st_lo ? e_lo : E - 1;
    const int eh = st_hi ? e_hi : E - 1;

    // batch dtype sniff: sorted values < G=256, so int64 => high word of last elem is 0
    const int* b32p = (const int*)batchv;
    const long long* b64p = (const long long*)batchv;
    const bool is64 = (b32p[E - 1] == 0);
    const long long g_lo = is64 ? b64p[el] : (long long)b32p[el];
    const long long g_hi = is64 ? b64p[eh] : (long long)b32p[eh];

    const float* ek_lo = ek  + (size_t)el * NEF;
    const float* ek_hi = ek  + (size_t)eh * NEF;
    const float* vr_lo = vrk + (size_t)el * NNF;
    const float* vr_hi = vrk + (size_t)eh * NNF;
    const float* vs_lo = vsk + (size_t)el * NNF;
    const float* vs_hi = vsk + (size_t)eh * NNF;
    const float* u_lo  = u   + (size_t)g_lo * NGF;
    const float* u_hi  = u   + (size_t)g_hi * NGF;

    // ---- layer 1: D1[16 rows x 128 cols] per warp ----
    float acc[16][4];
    #pragma unroll
    for (int nt = 0; nt < 16; ++nt)
        #pragma unroll
        for (int j = 0; j < 4; ++j) acc[nt][j] = 0.f;

    #pragma unroll
    for (int ks = 0; ks < 4; ++ks) KSTEP(ek_lo, ek_hi, ks * 16 + cb, ks);
    #pragma unroll
    for (int ks = 0; ks < 8; ++ks) KSTEP(vr_lo, vr_hi, ks * 16 + cb, ks + 4);
    #pragma unroll
    for (int ks = 0; ks < 8; ++ks) KSTEP(vs_lo, vs_hi, ks * 16 + cb, ks + 12);
    #pragma unroll
    for (int ks = 0; ks < 4; ++ks) KSTEP(u_lo, u_hi, ks * 16 + cb, ks + 20);

    // ---- epilogue 1 in registers: bias + relu + cvt -> layer-2 A fragments ----
    // C-frag (m16n8) layout == A-frag (m16n8k16) layout: nt pair (2j, 2j+1) => k-step j
    uint32_t hh[8][4];
    #pragma unroll
    for (int j = 0; j < 8; ++j) {
        float2 bA = *(const float2*)(b1 + 16 * j + cb);
        float2 bB = *(const float2*)(b1 + 16 * j + 8 + cb);
        float v00 = fmaxf(acc[2*j][0]   + bA.x, 0.f);
        float v01 = fmaxf(acc[2*j][1]   + bA.y, 0.f);
        float v10 = fmaxf(acc[2*j][2]   + bA.x, 0.f);
        float v11 = fmaxf(acc[2*j][3]   + bA.y, 0.f);
        float w00 = fmaxf(acc[2*j+1][0] + bB.x, 0.f);
        float w01 = fmaxf(acc[2*j+1][1] + bB.y, 0.f);
        float w10 = fmaxf(acc[2*j+1][2] + bB.x, 0.f);
        float w11 = fmaxf(acc[2*j+1][3] + bB.y, 0.f);
        hh[j][0] = f16x2(v00, v01);   // a0: row lo, k lo
        hh[j][1] = f16x2(v10, v11);   // a1: row hi, k lo
        hh[j][2] = f16x2(w00, w01);   // a2: row lo, k hi
        hh[j][3] = f16x2(w10, w11);   // a3: row hi, k hi
    }

    // ---- layer 2: D2[16 x 64] per warp, 8 n-tiles, K=128 (8 k-steps) ----
    float acc2[8][4];
    #pragma unroll
    for (int nt = 0; nt < 8; ++nt)
        #pragma unroll
        for (int j = 0; j < 4; ++j) acc2[nt][j] = 0.f;

    #pragma unroll
    for (int ks = 0; ks < 8; ++ks) {
        const uint4* wp = g_w2f4 + ks * 128 + lane;
        uint4 c0 = __ldg(wp);      uint4 c1 = __ldg(wp + 32);
        uint4 c2 = __ldg(wp + 64); uint4 c3 = __ldg(wp + 96);
        MMA(acc2[0], hh[ks][0], hh[ks][1], hh[ks][2], hh[ks][3], c0.x, c0.y);
        MMA(acc2[1], hh[ks][0], hh[ks][1], hh[ks][2], hh[ks][3], c0.z, c0.w);
        MMA(acc2[2], hh[ks][0], hh[ks][1], hh[ks][2], hh[ks][3], c1.x, c1.y);
        MMA(acc2[3], hh[ks][0], hh[ks][1], hh[ks][2], hh[ks][3], c1.z, c1.w);
        MMA(acc2[4], hh[ks][0], hh[ks][1], hh[ks][2], hh[ks][3], c2.x, c2.y);
        MMA(acc2[5], hh[ks][0], hh[ks][1], hh[ks][2], hh[ks][3], c2.z, c2.w);
        MMA(acc2[6], hh[ks][0], hh[ks][1], hh[ks][2], hh[ks][3], c3.x, c3.y);
        MMA(acc2[7], hh[ks][0], hh[ks][1], hh[ks][2], hh[ks][3], c3.z, c3.w);
    }

    // ---- store: + b2 ----
    #pragma unroll
    for (int nt = 0; nt < 8; ++nt) {
        float2 bb = *(const float2*)(b2 + nt * 8 + cb);
        if (st_lo)
            *(float2*)(out + (size_t)e_lo * TGT + nt * 8 + cb) =
                make_float2(acc2[nt][0] + bb.x, acc2[nt][1] + bb.y);
        if (st_hi)
            *(float2*)(out + (size_t)e_hi * TGT + nt * 8 + cb) =
                make_float2(acc2[nt][2] + bb.x, acc2[nt][3] + bb.y);
    }
}

extern "C" void kernel_launch(void* const* d_in, const int* in_sizes, int n_in,
                              void* d_out, int out_size)
{
    const float* ek    = (const float*)d_in[0];
    const float* vrk   = (const float*)d_in[1];
    const float* vsk   = (const float*)d_in[2];
    const float* u     = (const float*)d_in[3];
    const void*  batch = (const void*) d_in[4];
    const float* W1    = (const float*)d_in[5];
    const float* b1    = (const float*)d_in[6];
    const float* W2    = (const float*)d_in[7];
    const float* b2    = (const float*)d_in[8];
    float* out = (float*)d_out;

    const int E = in_sizes[0] / NEF;

    prep_frags<<<(24 * 8 * 32 + 8 * 4 * 32 + 255) / 256, 256>>>(W1, W2);

    const int grid = (E + TILE_E - 1) / TILE_E;
    edge_mlp_hmma<<<grid, 128>>>(ek, vrk, vsk, u, batch, b1, b2, out, E);
}